// round 10
// baseline (speedup 1.0000x reference)
#include <cuda_runtime.h>
#include <cstdint>
#include <cstddef>

#define B_   32
#define S_   512
#define E_   512
#define H_   1024
#define V_   5000
#define G4_  4096
#define MR_  16384      // B*S
#define NCTA 128        // persistent LSTM CTAs

// ---------------------------------------------------------------------------
// Static device scratch (allocation-free per harness rules)
// ---------------------------------------------------------------------------
__device__ float    g_xg[(size_t)MR_ * G4_];     // [B,S,4H] input-gate precompute
__device__ unsigned g_htf[(size_t)MR_ * H_];     // [B,S,H] hidden states, tf32 bits
__device__ unsigned g_hzero[B_ * H_];            // zero h_{-1} (tf32 bits of 0.0)
__device__ unsigned g_arr[8 * 32];               // 8 arrival counters, 128B apart
__device__ unsigned g_release;                   // barrier release flag

// ---------------------------------------------------------------------------
// tf32 / mma / ldmatrix / cp.async helpers
// ---------------------------------------------------------------------------
__device__ __forceinline__ unsigned f2tf(float x) {
    unsigned r;
    asm("cvt.rna.tf32.f32 %0, %1;" : "=r"(r) : "f"(x));
    return r;
}

__device__ __forceinline__ void mma8(float* c, const unsigned* a, const unsigned* b) {
    asm volatile(
        "mma.sync.aligned.m16n8k8.row.col.f32.tf32.tf32.f32 "
        "{%0,%1,%2,%3},{%4,%5,%6,%7},{%8,%9},{%0,%1,%2,%3};\n"
        : "+f"(c[0]), "+f"(c[1]), "+f"(c[2]), "+f"(c[3])
        : "r"(a[0]), "r"(a[1]), "r"(a[2]), "r"(a[3]), "r"(b[0]), "r"(b[1]));
}

// x4 b16 ldmatrix: 4 m8n8 b16 matrices == 2 8x8 f32 tiles -> tf32 fragments.
__device__ __forceinline__ void ldsm4(unsigned* r, const void* smem_ptr) {
    unsigned a = (unsigned)__cvta_generic_to_shared(smem_ptr);
    asm volatile("ldmatrix.sync.aligned.m8n8.x4.shared.b16 {%0,%1,%2,%3}, [%4];\n"
                 : "=r"(r[0]), "=r"(r[1]), "=r"(r[2]), "=r"(r[3]) : "r"(a));
}

__device__ __forceinline__ void cpasync16(void* smem, const void* g) {
    unsigned s = (unsigned)__cvta_generic_to_shared(smem);
    asm volatile("cp.async.cg.shared.global [%0], [%1], 16;\n" :: "r"(s), "l"(g));
}
__device__ __forceinline__ void cp_commit() {
    asm volatile("cp.async.commit_group;\n" ::: "memory");
}
__device__ __forceinline__ void cp_wait1() {
    asm volatile("cp.async.wait_group 1;\n" ::: "memory");
}
__device__ __forceinline__ void cp_wait0() {
    asm volatile("cp.async.wait_group 0;\n" ::: "memory");
}

__device__ __forceinline__ float fsigmoid(float x) {
    return __fdividef(1.f, 1.f + __expf(-x));
}
__device__ __forceinline__ float ftanh(float x) {
    return __fdividef(2.f, 1.f + __expf(-2.f * x)) - 1.f;
}

// ---------------------------------------------------------------------------
// Generic tf32 GEMM: C[M,N] = A[M,K] @ Wt[N,K]^T (+bias). Optional gather on A.
// ATF32: A already holds tf32 bit patterns (skip convert).
// BM=BN=128, BK=16, 256 threads, 8 warps in 2(m) x 4(n), warp tile 64x32.
// Fragment loads via ldmatrix.x4.b16.
// ---------------------------------------------------------------------------
#define BM 128
#define BN 128
#define BK 16

template<bool GATHER, bool ATF32, int NBIAS>
__global__ __launch_bounds__(256)
void gemm_tf32(const float* __restrict__ A, const int* __restrict__ idx,
               const float* __restrict__ Wt, const float* __restrict__ b0p,
               const float* __restrict__ b1p, float* __restrict__ C,
               int M, int N, int K)
{
    __shared__ __align__(16) unsigned As[2][BM][BK + 4];   // row stride 80B (16B mult)
    __shared__ __align__(16) unsigned Bs[2][BN][BK + 4];

    const int tid  = threadIdx.x;
    const int lane = tid & 31, warp = tid >> 5;
    const int wm   = warp & 1,  wn  = warp >> 1;
    const int quad = lane >> 2, tq  = lane & 3;
    const int m0   = blockIdx.y * BM, n0 = blockIdx.x * BN;
    const int lrow = tid >> 2;          // 0..63
    const int lk   = (tid & 3) * 4;     // 0,4,8,12

    // ldmatrix per-lane address roles
    const int arow  = wm * 64 + (lane & 15);          // A: rows, +mi*16
    const int acol4 = (lane >> 4) * 4;                //    k sub-offset
    const int brow  = wn * 32 + (lane & 7) + ((lane >> 4) & 1) * 8;  // B: + p*16
    const int bcol4 = ((lane >> 3) & 1) * 4;

    const float* ap[2];
    const float* bp[2];
    bool bv[2];
#pragma unroll
    for (int i = 0; i < 2; i++) {
        int m = m0 + lrow + 64 * i;
        int gidx = GATHER ? idx[m] : m;
        ap[i] = A + (size_t)gidx * K + lk;
        int n = n0 + lrow + 64 * i;
        bv[i] = (n < N);
        bp[i] = Wt + (size_t)(bv[i] ? n : 0) * K + lk;
    }

    float acc[4][4][4];
#pragma unroll
    for (int mi = 0; mi < 4; mi++)
#pragma unroll
        for (int nj = 0; nj < 4; nj++)
#pragma unroll
            for (int r = 0; r < 4; r++) acc[mi][nj][r] = 0.f;

    // stage 0
#pragma unroll
    for (int i = 0; i < 2; i++) {
        uint4 ra = *(const uint4*)ap[i];
        if (!ATF32)
            ra = make_uint4(f2tf(__uint_as_float(ra.x)), f2tf(__uint_as_float(ra.y)),
                            f2tf(__uint_as_float(ra.z)), f2tf(__uint_as_float(ra.w)));
        *(uint4*)&As[0][lrow + 64 * i][lk] = ra;
        float4 vb = make_float4(0.f, 0.f, 0.f, 0.f);
        if (bv[i]) vb = *(const float4*)bp[i];
        *(uint4*)&Bs[0][lrow + 64 * i][lk] =
            make_uint4(f2tf(vb.x), f2tf(vb.y), f2tf(vb.z), f2tf(vb.w));
    }
    __syncthreads();

    const int KT = K / BK;
    for (int kt = 0; kt < KT; kt++) {
        const int buf = kt & 1;
        uint4  na[2];
        float4 nb[2];
        if (kt + 1 < KT) {
#pragma unroll
            for (int i = 0; i < 2; i++) {
                na[i] = *(const uint4*)(ap[i] + (kt + 1) * BK);
                nb[i] = make_float4(0.f, 0.f, 0.f, 0.f);
                if (bv[i]) nb[i] = *(const float4*)(bp[i] + (kt + 1) * BK);
            }
        }
#pragma unroll
        for (int ks = 0; ks < 2; ks++) {
            const int k0 = ks * 8;
            unsigned a[4][4], bb[2][4];
#pragma unroll
            for (int mi = 0; mi < 4; mi++)
                ldsm4(a[mi], &As[buf][arow + mi * 16][k0 + acol4]);
#pragma unroll
            for (int p = 0; p < 2; p++)
                ldsm4(bb[p], &Bs[buf][brow + p * 16][k0 + bcol4]);
#pragma unroll
            for (int mi = 0; mi < 4; mi++)
#pragma unroll
                for (int nj = 0; nj < 4; nj++)
                    mma8(acc[mi][nj], a[mi], &bb[nj >> 1][(nj & 1) * 2]);
        }
        if (kt + 1 < KT) {
#pragma unroll
            for (int i = 0; i < 2; i++) {
                uint4 ra = na[i];
                if (!ATF32)
                    ra = make_uint4(f2tf(__uint_as_float(ra.x)), f2tf(__uint_as_float(ra.y)),
                                    f2tf(__uint_as_float(ra.z)), f2tf(__uint_as_float(ra.w)));
                *(uint4*)&As[buf ^ 1][lrow + 64 * i][lk] = ra;
                *(uint4*)&Bs[buf ^ 1][lrow + 64 * i][lk] =
                    make_uint4(f2tf(nb[i].x), f2tf(nb[i].y), f2tf(nb[i].z), f2tf(nb[i].w));
            }
            __syncthreads();
        }
    }

    // epilogue (+bias); N even, col even -> col+1 < N implied by col < N
#pragma unroll
    for (int mi = 0; mi < 4; mi++) {
        const int row = m0 + wm * 64 + mi * 16 + quad;
#pragma unroll
        for (int nj = 0; nj < 4; nj++) {
            const int col = n0 + wn * 32 + nj * 8 + tq * 2;
            if (col < N) {
                float bb0 = 0.f, bb1 = 0.f;
                if (NBIAS >= 1) { bb0 = b0p[col];  bb1 = b0p[col + 1]; }
                if (NBIAS >= 2) { bb0 += b1p[col]; bb1 += b1p[col + 1]; }
                float2 v0 = make_float2(acc[mi][nj][0] + bb0, acc[mi][nj][1] + bb1);
                float2 v1 = make_float2(acc[mi][nj][2] + bb0, acc[mi][nj][3] + bb1);
                *(float2*)(C + (size_t)row * N + col)       = v0;
                *(float2*)(C + (size_t)(row + 8) * N + col) = v1;
            }
        }
    }
}

// ---------------------------------------------------------------------------
__global__ void reset_kernel() {
#pragma unroll
    for (int i = 0; i < 8; i++) g_arr[i * 32] = 0u;
    g_release = 0u;
}

// ---------------------------------------------------------------------------
// Persistent LSTM recurrence. 128 CTAs x 256 threads. CTA owns hidden dims
// [cta*8, cta*8+8). Gate rows are INTERLEAVED in smem: row r <-> (gate=r&3,
// dim=r>>2), so each thread's 4 gate partials are one contiguous float4.
// Warp w owns K-slice [w*128, w*128+128): stages its slice via cp.async in
// four 32-k sub-chunks (2 rotating warp-private buffers), per-warp wait_group
// + __syncwarp; fragments via ldmatrix.x4.b16.
// Grid barrier: 8 arrival counters on separate L2 lines + leader-published
// release flag (kills single-address atomic serialization).
// smem: Ws [32][1028] tf32 (131584B) + hbuf [8][2][32][36] (73728B) = 205312B.
// Partial buffer [8][32][40] f32 aliases hbuf after the MMA phase.
// ---------------------------------------------------------------------------
#define WS_STR   1028
#define HB_STRD  36
#define HB_BUF   (32 * HB_STRD)         // 1152 u32 per buffer
#define HB_WARP  (2 * HB_BUF)           // 2304 u32 per warp
#define PART_STR 40
#define SMEM_LSTM (32 * WS_STR * 4 + 8 * HB_WARP * 4)   // 205312

__global__ __launch_bounds__(256, 1)
void lstm_kernel(const float* __restrict__ W_hh)
{
    extern __shared__ unsigned sd[];
    unsigned* Ws = sd;                       // [32][1028]
    unsigned* hb = sd + 32 * WS_STR;         // [8][2][32][36]
    float* part  = (float*)hb;               // [8][32][40] (aliases hb)

    const int tid  = threadIdx.x;
    const int lane = tid & 31, warp = tid >> 5;
    const int j0   = blockIdx.x * 8;
    const int bb   = tid >> 3, jj = tid & 7;   // activation (batch, dim)
    const int srow = lane >> 3, su = lane & 7; // staging lane roles
    const int kb   = warp * 128;               // warp K-slice base

    // ldmatrix per-lane address roles
    const int arow  = lane & 15;                                   // + mi*16
    const int acol4 = (lane >> 4) * 4;
    const int brow  = (lane & 7) + ((lane >> 4) & 1) * 8;          // + p*16
    const int bcol4 = ((lane >> 3) & 1) * 4;

    // Load W_hh slice -> tf32 smem (once), gate-interleaved rows:
    // smem row r holds W_hh row gate*H + j0 + dim, gate = r&3, dim = r>>2.
    {
        const int r8 = tid >> 3, t8 = tid & 7;
        const int gate = r8 & 3, jr = r8 >> 2;
        const float* wrow = W_hh + (size_t)(gate * H_ + j0 + jr) * H_ + t8 * 128;
        unsigned* dst = Ws + r8 * WS_STR + t8 * 128;
#pragma unroll 8
        for (int i = 0; i < 32; i++) {
            float4 v = *(const float4*)(wrow + i * 4);
            dst[i * 4 + 0] = f2tf(v.x); dst[i * 4 + 1] = f2tf(v.y);
            dst[i * 4 + 2] = f2tf(v.z); dst[i * 4 + 3] = f2tf(v.w);
        }
    }
    __syncthreads();

    unsigned* hw = hb + warp * HB_WARP;
    float c = 0.f;
    const size_t xbase = ((size_t)bb * S_) * G4_ + j0 + jj;

    // prefetch xg for step 0 (DRAM; consumed after the step-0 reduce)
    float x0 = __ldcs(&g_xg[xbase]);
    float x1 = __ldcs(&g_xg[xbase + H_]);
    float x2 = __ldcs(&g_xg[xbase + 2 * H_]);
    float x3 = __ldcs(&g_xg[xbase + 3 * H_]);

    for (int t = 0; t < S_; t++) {
        // per-lane staging source: row = i*4 + srow, col = kb + s*32 + su*4
        const size_t rstep = (t == 0) ? (size_t)4 * H_ : (size_t)4 * S_ * H_;
        const unsigned* hbase = (t == 0)
            ? g_hzero + (size_t)srow * H_ + kb + su * 4
            : g_htf + (size_t)(t - 1) * H_ + (size_t)srow * S_ * H_ + kb + su * 4;

        float acc[2][4][4];
#pragma unroll
        for (int mi = 0; mi < 2; mi++)
#pragma unroll
            for (int nj = 0; nj < 4; nj++)
#pragma unroll
                for (int r = 0; r < 4; r++) acc[mi][nj][r] = 0.f;

        // stage sub-chunks 0,1 (warp-private)
#pragma unroll
        for (int s = 0; s < 2; s++) {
            unsigned* dst = hw + (s & 1) * HB_BUF + srow * HB_STRD + su * 4;
            const unsigned* src = hbase + s * 32;
#pragma unroll
            for (int i = 0; i < 8; i++)
                cpasync16(dst + i * 4 * HB_STRD, src + i * rstep);
            cp_commit();
        }

#pragma unroll
        for (int s = 0; s < 4; s++) {
            if (s < 3) cp_wait1(); else cp_wait0();
            __syncwarp();                               // sub-chunk s resident (warp-wide)
            const unsigned* hbb = hw + (s & 1) * HB_BUF;
#pragma unroll
            for (int kt = 0; kt < 4; kt++) {
                const int k0 = kt * 8;
                const int wk0 = kb + s * 32 + k0;
                unsigned a[2][4], bw[2][4];
#pragma unroll
                for (int mi = 0; mi < 2; mi++)
                    ldsm4(a[mi], &hbb[(mi * 16 + arow) * HB_STRD + k0 + acol4]);
#pragma unroll
                for (int p = 0; p < 2; p++)
                    ldsm4(bw[p], &Ws[(p * 16 + brow) * WS_STR + wk0 + bcol4]);
#pragma unroll
                for (int mi = 0; mi < 2; mi++)
#pragma unroll
                    for (int nj = 0; nj < 4; nj++)
                        mma8(acc[mi][nj], a[mi], &bw[nj >> 1][(nj & 1) * 2]);
            }
            if (s + 2 < 4) {
                __syncwarp();                           // warp done reading this buf
                unsigned* dst = hw + (s & 1) * HB_BUF + srow * HB_STRD + su * 4;
                const unsigned* src = hbase + (s + 2) * 32;
#pragma unroll
                for (int i = 0; i < 8; i++)
                    cpasync16(dst + i * 4 * HB_STRD, src + i * rstep);
                cp_commit();
            }
        }
        __syncthreads();               // all warps done with hbuf -> alias as part

        // per-warp partials: part[warp][batch][40]
        {
            const int quad = lane >> 2, tq = lane & 3;
#pragma unroll
            for (int mi = 0; mi < 2; mi++)
#pragma unroll
                for (int nj = 0; nj < 4; nj++) {
                    float* p0 = part + warp * (32 * PART_STR)
                              + (mi * 16 + quad) * PART_STR + nj * 8 + tq * 2;
                    *(float2*)p0                  = make_float2(acc[mi][nj][0], acc[mi][nj][1]);
                    *(float2*)(p0 + 8 * PART_STR) = make_float2(acc[mi][nj][2], acc[mi][nj][3]);
                }
        }
        __syncthreads();

        // activations: thread owns (batch bb, dim jj); gate-interleaved cols
        // make the 4 partials one float4 at col jj*4.
        {
            float s0 = x0, s1 = x1, s2 = x2, s3 = x3;
#pragma unroll
            for (int w = 0; w < 8; w++) {
                const float4 p = *(const float4*)(part + w * (32 * PART_STR)
                                                  + bb * PART_STR + jj * 4);
                s0 += p.x; s1 += p.y; s2 += p.z; s3 += p.w;
            }
            const float si = fsigmoid(s0);
            const float sf = fsigmoid(s1);
            const float gg = ftanh(s2);
            const float so = fsigmoid(s3);
            c = sf * c + si * gg;
            const float h = so * ftanh(c);
            g_htf[((size_t)bb * S_ + t) * H_ + j0 + jj] = f2tf(h);
        }

        // prefetch xg for t+1 BEFORE the barrier (latency hides behind spin)
        if (t + 1 < S_) {
            const size_t xrow = xbase + (size_t)(t + 1) * G4_;
            x0 = __ldcs(&g_xg[xrow]);
            x1 = __ldcs(&g_xg[xrow + H_]);
            x2 = __ldcs(&g_xg[xrow + 2 * H_]);
            x3 = __ldcs(&g_xg[xrow + 3 * H_]);
        }

        // hierarchical grid barrier: 8 spread counters + leader release
        __syncthreads();
        if (tid == 0) {
            __threadfence();
            atomicAdd(&g_arr[(blockIdx.x & 7) * 32], 1u);
            const unsigned tgt = (unsigned)(t + 1);
            if (blockIdx.x == 0) {
                for (;;) {
                    unsigned ssum = 0;
#pragma unroll
                    for (int i = 0; i < 8; i++)
                        ssum += *(volatile unsigned*)&g_arr[i * 32];
                    if (ssum >= tgt * NCTA) break;
                }
                __threadfence();
                *(volatile unsigned*)&g_release = tgt;
            } else {
                while (*(volatile unsigned*)&g_release < tgt) { }
            }
            __threadfence();
        }
        __syncthreads();
    }
}

// ---------------------------------------------------------------------------
extern "C" void kernel_launch(void* const* d_in, const int* in_sizes, int n_in,
                              void* d_out, int out_size)
{
    const int*   x    = (const int*)  d_in[0];
    const float* emb  = (const float*)d_in[1];
    const float* W_ih = (const float*)d_in[2];
    const float* W_hh = (const float*)d_in[3];
    const float* b_ih = (const float*)d_in[4];
    const float* b_hh = (const float*)d_in[5];
    const float* W_fc = (const float*)d_in[6];
    const float* b_fc = (const float*)d_in[7];
    float* out = (float*)d_out;

    float *p_xg; unsigned *p_htf;
    cudaGetSymbolAddress((void**)&p_xg,  g_xg);
    cudaGetSymbolAddress((void**)&p_htf, g_htf);
    cudaFuncSetAttribute(lstm_kernel,
                         cudaFuncAttributeMaxDynamicSharedMemorySize, SMEM_LSTM);

    // Phase 1: xg = emb[x] @ W_ih^T + b_ih + b_hh   [16384 x 4096], K=512
    gemm_tf32<true, false, 2><<<dim3(G4_ / BN, MR_ / BM), 256>>>(
        emb, x, W_ih, b_ih, b_hh, p_xg, MR_, G4_, E_);

    // Phase 2: recurrence (persistent, grid-barriered)
    reset_kernel<<<1, 1>>>();
    lstm_kernel<<<NCTA, 256, SMEM_LSTM>>>(W_hh);

    // Phase 3: logits = h @ W_fc^T + b_fc   [16384 x 5000], K=1024 (A is tf32 bits)
    gemm_tf32<false, true, 1><<<dim3((V_ + BN - 1) / BN, MR_ / BM), 256>>>(
        (const float*)p_htf, nullptr, W_fc, b_fc, nullptr, out, MR_, V_, H_);
}

// round 14
// speedup vs baseline: 1.0930x; 1.0930x over previous
#include <cuda_runtime.h>
#include <cstdint>
#include <cstddef>

#define B_   32
#define S_   512
#define E_   512
#define H_   1024
#define V_   5000
#define G4_  4096
#define MR_  16384      // B*S
#define NCTA 128        // persistent LSTM CTAs

// ---------------------------------------------------------------------------
// Static device scratch (allocation-free per harness rules)
// ---------------------------------------------------------------------------
__device__ float    g_xg[(size_t)MR_ * G4_];     // [B,S,4H] input-gate precompute
__device__ unsigned g_htf[(size_t)MR_ * H_];     // [B,S,H] hidden states, tf32 bits
__device__ unsigned g_hzero[B_ * H_];            // zero h_{-1} (tf32 bits of 0.0)
__device__ unsigned g_arrive;                    // grid-barrier arrival counter

// ---------------------------------------------------------------------------
// tf32 / mma / ldmatrix / cp.async helpers
// ---------------------------------------------------------------------------
__device__ __forceinline__ unsigned f2tf(float x) {
    unsigned r;
    asm("cvt.rna.tf32.f32 %0, %1;" : "=r"(r) : "f"(x));
    return r;
}

__device__ __forceinline__ void mma8(float* c, const unsigned* a, const unsigned* b) {
    asm volatile(
        "mma.sync.aligned.m16n8k8.row.col.f32.tf32.tf32.f32 "
        "{%0,%1,%2,%3},{%4,%5,%6,%7},{%8,%9},{%0,%1,%2,%3};\n"
        : "+f"(c[0]), "+f"(c[1]), "+f"(c[2]), "+f"(c[3])
        : "r"(a[0]), "r"(a[1]), "r"(a[2]), "r"(a[3]), "r"(b[0]), "r"(b[1]));
}

// x4 b16 ldmatrix: 4 m8n8 b16 matrices == 2 8x8 f32 tiles -> tf32 fragments.
__device__ __forceinline__ void ldsm4(unsigned* r, const void* smem_ptr) {
    unsigned a = (unsigned)__cvta_generic_to_shared(smem_ptr);
    asm volatile("ldmatrix.sync.aligned.m8n8.x4.shared.b16 {%0,%1,%2,%3}, [%4];\n"
                 : "=r"(r[0]), "=r"(r[1]), "=r"(r[2]), "=r"(r[3]) : "r"(a));
}

__device__ __forceinline__ void cpasync16(void* smem, const void* g) {
    unsigned s = (unsigned)__cvta_generic_to_shared(smem);
    asm volatile("cp.async.cg.shared.global [%0], [%1], 16;\n" :: "r"(s), "l"(g));
}
__device__ __forceinline__ void cp_commit() {
    asm volatile("cp.async.commit_group;\n" ::: "memory");
}
__device__ __forceinline__ void cp_wait1() {
    asm volatile("cp.async.wait_group 1;\n" ::: "memory");
}
__device__ __forceinline__ void cp_wait0() {
    asm volatile("cp.async.wait_group 0;\n" ::: "memory");
}

__device__ __forceinline__ float fsigmoid(float x) {
    return __fdividef(1.f, 1.f + __expf(-x));
}
__device__ __forceinline__ float ftanh(float x) {
    return __fdividef(2.f, 1.f + __expf(-2.f * x)) - 1.f;
}

// ---------------------------------------------------------------------------
// Generic tf32 GEMM: C[M,N] = A[M,K] @ Wt[N,K]^T (+bias). Optional gather on A.
// ATF32: A already holds tf32 bit patterns (skip convert).
// BM=BN=128, BK=16, 256 threads, 8 warps in 2(m) x 4(n), warp tile 64x32.
// Fragment loads via ldmatrix.x4.b16.
// ---------------------------------------------------------------------------
#define BM 128
#define BN 128
#define BK 16

template<bool GATHER, bool ATF32, int NBIAS>
__global__ __launch_bounds__(256)
void gemm_tf32(const float* __restrict__ A, const int* __restrict__ idx,
               const float* __restrict__ Wt, const float* __restrict__ b0p,
               const float* __restrict__ b1p, float* __restrict__ C,
               int M, int N, int K)
{
    __shared__ __align__(16) unsigned As[2][BM][BK + 4];   // row stride 80B (16B mult)
    __shared__ __align__(16) unsigned Bs[2][BN][BK + 4];

    const int tid  = threadIdx.x;
    const int lane = tid & 31, warp = tid >> 5;
    const int wm   = warp & 1,  wn  = warp >> 1;
    const int quad = lane >> 2, tq  = lane & 3;
    const int m0   = blockIdx.y * BM, n0 = blockIdx.x * BN;
    const int lrow = tid >> 2;          // 0..63
    const int lk   = (tid & 3) * 4;     // 0,4,8,12

    // ldmatrix per-lane address roles
    const int arow  = wm * 64 + (lane & 15);          // A: rows, +mi*16
    const int acol4 = (lane >> 4) * 4;                //    k sub-offset
    const int brow  = wn * 32 + (lane & 7) + ((lane >> 4) & 1) * 8;  // B: + p*16
    const int bcol4 = ((lane >> 3) & 1) * 4;

    const float* ap[2];
    const float* bp[2];
    bool bv[2];
#pragma unroll
    for (int i = 0; i < 2; i++) {
        int m = m0 + lrow + 64 * i;
        int gidx = GATHER ? idx[m] : m;
        ap[i] = A + (size_t)gidx * K + lk;
        int n = n0 + lrow + 64 * i;
        bv[i] = (n < N);
        bp[i] = Wt + (size_t)(bv[i] ? n : 0) * K + lk;
    }

    float acc[4][4][4];
#pragma unroll
    for (int mi = 0; mi < 4; mi++)
#pragma unroll
        for (int nj = 0; nj < 4; nj++)
#pragma unroll
            for (int r = 0; r < 4; r++) acc[mi][nj][r] = 0.f;

    // stage 0
#pragma unroll
    for (int i = 0; i < 2; i++) {
        uint4 ra = *(const uint4*)ap[i];
        if (!ATF32)
            ra = make_uint4(f2tf(__uint_as_float(ra.x)), f2tf(__uint_as_float(ra.y)),
                            f2tf(__uint_as_float(ra.z)), f2tf(__uint_as_float(ra.w)));
        *(uint4*)&As[0][lrow + 64 * i][lk] = ra;
        float4 vb = make_float4(0.f, 0.f, 0.f, 0.f);
        if (bv[i]) vb = *(const float4*)bp[i];
        *(uint4*)&Bs[0][lrow + 64 * i][lk] =
            make_uint4(f2tf(vb.x), f2tf(vb.y), f2tf(vb.z), f2tf(vb.w));
    }
    __syncthreads();

    const int KT = K / BK;
    for (int kt = 0; kt < KT; kt++) {
        const int buf = kt & 1;
        uint4  na[2];
        float4 nb[2];
        if (kt + 1 < KT) {
#pragma unroll
            for (int i = 0; i < 2; i++) {
                na[i] = *(const uint4*)(ap[i] + (kt + 1) * BK);
                nb[i] = make_float4(0.f, 0.f, 0.f, 0.f);
                if (bv[i]) nb[i] = *(const float4*)(bp[i] + (kt + 1) * BK);
            }
        }
#pragma unroll
        for (int ks = 0; ks < 2; ks++) {
            const int k0 = ks * 8;
            unsigned a[4][4], bb[2][4];
#pragma unroll
            for (int mi = 0; mi < 4; mi++)
                ldsm4(a[mi], &As[buf][arow + mi * 16][k0 + acol4]);
#pragma unroll
            for (int p = 0; p < 2; p++)
                ldsm4(bb[p], &Bs[buf][brow + p * 16][k0 + bcol4]);
#pragma unroll
            for (int mi = 0; mi < 4; mi++)
#pragma unroll
                for (int nj = 0; nj < 4; nj++)
                    mma8(acc[mi][nj], a[mi], &bb[nj >> 1][(nj & 1) * 2]);
        }
        if (kt + 1 < KT) {
#pragma unroll
            for (int i = 0; i < 2; i++) {
                uint4 ra = na[i];
                if (!ATF32)
                    ra = make_uint4(f2tf(__uint_as_float(ra.x)), f2tf(__uint_as_float(ra.y)),
                                    f2tf(__uint_as_float(ra.z)), f2tf(__uint_as_float(ra.w)));
                *(uint4*)&As[buf ^ 1][lrow + 64 * i][lk] = ra;
                *(uint4*)&Bs[buf ^ 1][lrow + 64 * i][lk] =
                    make_uint4(f2tf(nb[i].x), f2tf(nb[i].y), f2tf(nb[i].z), f2tf(nb[i].w));
            }
            __syncthreads();
        }
    }

    // epilogue (+bias); N even, col even -> col+1 < N implied by col < N
#pragma unroll
    for (int mi = 0; mi < 4; mi++) {
        const int row = m0 + wm * 64 + mi * 16 + quad;
#pragma unroll
        for (int nj = 0; nj < 4; nj++) {
            const int col = n0 + wn * 32 + nj * 8 + tq * 2;
            if (col < N) {
                float bb0 = 0.f, bb1 = 0.f;
                if (NBIAS >= 1) { bb0 = b0p[col];  bb1 = b0p[col + 1]; }
                if (NBIAS >= 2) { bb0 += b1p[col]; bb1 += b1p[col + 1]; }
                float2 v0 = make_float2(acc[mi][nj][0] + bb0, acc[mi][nj][1] + bb1);
                float2 v1 = make_float2(acc[mi][nj][2] + bb0, acc[mi][nj][3] + bb1);
                *(float2*)(C + (size_t)row * N + col)       = v0;
                *(float2*)(C + (size_t)(row + 8) * N + col) = v1;
            }
        }
    }
}

// ---------------------------------------------------------------------------
__global__ void reset_kernel() { g_arrive = 0u; }

// ---------------------------------------------------------------------------
// Persistent LSTM recurrence. 128 CTAs x 256 threads. CTA owns hidden dims
// [cta*8, cta*8+8). Gate rows are INTERLEAVED in smem: row r <-> (gate=r&3,
// dim=r>>2), so each thread's 4 gate partials are one contiguous float4.
// Warp w owns K-slice [w*128, w*128+128): stages its slice via cp.async in
// four 32-k sub-chunks (2 rotating warp-private buffers), per-warp wait_group
// + __syncwarp; fragments via ldmatrix.x4.b16.
// Grid barrier: single monotone counter (R7 form — measured fastest).
// smem: Ws [32][1028] tf32 (131584B) + hbuf [8][2][32][36] (73728B) = 205312B.
// Partial buffer [8][32][40] f32 aliases hbuf after the MMA phase.
// ---------------------------------------------------------------------------
#define WS_STR   1028
#define HB_STRD  36
#define HB_BUF   (32 * HB_STRD)         // 1152 u32 per buffer
#define HB_WARP  (2 * HB_BUF)           // 2304 u32 per warp
#define PART_STR 40
#define SMEM_LSTM (32 * WS_STR * 4 + 8 * HB_WARP * 4)   // 205312

__global__ __launch_bounds__(256, 1)
void lstm_kernel(const float* __restrict__ W_hh)
{
    extern __shared__ unsigned sd[];
    unsigned* Ws = sd;                       // [32][1028]
    unsigned* hb = sd + 32 * WS_STR;         // [8][2][32][36]
    float* part  = (float*)hb;               // [8][32][40] (aliases hb)

    const int tid  = threadIdx.x;
    const int lane = tid & 31, warp = tid >> 5;
    const int j0   = blockIdx.x * 8;
    const int bb   = tid >> 3, jj = tid & 7;   // activation (batch, dim)
    const int srow = lane >> 3, su = lane & 7; // staging lane roles
    const int kb   = warp * 128;               // warp K-slice base

    // ldmatrix per-lane address roles
    const int arow  = lane & 15;                                   // + mi*16
    const int acol4 = (lane >> 4) * 4;
    const int brow  = (lane & 7) + ((lane >> 4) & 1) * 8;          // + p*16
    const int bcol4 = ((lane >> 3) & 1) * 4;

    // Load W_hh slice -> tf32 smem (once), gate-interleaved rows:
    // smem row r holds W_hh row gate*H + j0 + dim, gate = r&3, dim = r>>2.
    {
        const int r8 = tid >> 3, t8 = tid & 7;
        const int gate = r8 & 3, jr = r8 >> 2;
        const float* wrow = W_hh + (size_t)(gate * H_ + j0 + jr) * H_ + t8 * 128;
        unsigned* dst = Ws + r8 * WS_STR + t8 * 128;
#pragma unroll 8
        for (int i = 0; i < 32; i++) {
            float4 v = *(const float4*)(wrow + i * 4);
            dst[i * 4 + 0] = f2tf(v.x); dst[i * 4 + 1] = f2tf(v.y);
            dst[i * 4 + 2] = f2tf(v.z); dst[i * 4 + 3] = f2tf(v.w);
        }
    }
    __syncthreads();

    unsigned* hw = hb + warp * HB_WARP;
    float c = 0.f;
    const size_t xbase = ((size_t)bb * S_) * G4_ + j0 + jj;

    // prefetch xg for step 0 (DRAM; consumed after the step-0 reduce)
    float x0 = __ldcs(&g_xg[xbase]);
    float x1 = __ldcs(&g_xg[xbase + H_]);
    float x2 = __ldcs(&g_xg[xbase + 2 * H_]);
    float x3 = __ldcs(&g_xg[xbase + 3 * H_]);

    for (int t = 0; t < S_; t++) {
        // per-lane staging source: row = i*4 + srow, col = kb + s*32 + su*4
        const size_t rstep = (t == 0) ? (size_t)4 * H_ : (size_t)4 * S_ * H_;
        const unsigned* hbase = (t == 0)
            ? g_hzero + (size_t)srow * H_ + kb + su * 4
            : g_htf + (size_t)(t - 1) * H_ + (size_t)srow * S_ * H_ + kb + su * 4;

        float acc[2][4][4];
#pragma unroll
        for (int mi = 0; mi < 2; mi++)
#pragma unroll
            for (int nj = 0; nj < 4; nj++)
#pragma unroll
                for (int r = 0; r < 4; r++) acc[mi][nj][r] = 0.f;

        // stage sub-chunks 0,1 (warp-private)
#pragma unroll
        for (int s = 0; s < 2; s++) {
            unsigned* dst = hw + (s & 1) * HB_BUF + srow * HB_STRD + su * 4;
            const unsigned* src = hbase + s * 32;
#pragma unroll
            for (int i = 0; i < 8; i++)
                cpasync16(dst + i * 4 * HB_STRD, src + i * rstep);
            cp_commit();
        }

#pragma unroll
        for (int s = 0; s < 4; s++) {
            if (s < 3) cp_wait1(); else cp_wait0();
            __syncwarp();                               // sub-chunk s resident (warp-wide)
            const unsigned* hbb = hw + (s & 1) * HB_BUF;
#pragma unroll
            for (int kt = 0; kt < 4; kt++) {
                const int k0 = kt * 8;
                const int wk0 = kb + s * 32 + k0;
                unsigned a[2][4], bw[2][4];
#pragma unroll
                for (int mi = 0; mi < 2; mi++)
                    ldsm4(a[mi], &hbb[(mi * 16 + arow) * HB_STRD + k0 + acol4]);
#pragma unroll
                for (int p = 0; p < 2; p++)
                    ldsm4(bw[p], &Ws[(p * 16 + brow) * WS_STR + wk0 + bcol4]);
#pragma unroll
                for (int mi = 0; mi < 2; mi++)
#pragma unroll
                    for (int nj = 0; nj < 4; nj++)
                        mma8(acc[mi][nj], a[mi], &bw[nj >> 1][(nj & 1) * 2]);
            }
            if (s + 2 < 4) {
                __syncwarp();                           // warp done reading this buf
                unsigned* dst = hw + (s & 1) * HB_BUF + srow * HB_STRD + su * 4;
                const unsigned* src = hbase + (s + 2) * 32;
#pragma unroll
                for (int i = 0; i < 8; i++)
                    cpasync16(dst + i * 4 * HB_STRD, src + i * rstep);
                cp_commit();
            }
        }
        __syncthreads();               // all warps done with hbuf -> alias as part

        // per-warp partials: part[warp][batch][40]
        {
            const int quad = lane >> 2, tq = lane & 3;
#pragma unroll
            for (int mi = 0; mi < 2; mi++)
#pragma unroll
                for (int nj = 0; nj < 4; nj++) {
                    float* p0 = part + warp * (32 * PART_STR)
                              + (mi * 16 + quad) * PART_STR + nj * 8 + tq * 2;
                    *(float2*)p0                  = make_float2(acc[mi][nj][0], acc[mi][nj][1]);
                    *(float2*)(p0 + 8 * PART_STR) = make_float2(acc[mi][nj][2], acc[mi][nj][3]);
                }
        }
        __syncthreads();

        // activations: thread owns (batch bb, dim jj); gate-interleaved cols
        // make the 4 partials one float4 at col jj*4.
        {
            float s0 = x0, s1 = x1, s2 = x2, s3 = x3;
#pragma unroll
            for (int w = 0; w < 8; w++) {
                const float4 p = *(const float4*)(part + w * (32 * PART_STR)
                                                  + bb * PART_STR + jj * 4);
                s0 += p.x; s1 += p.y; s2 += p.z; s3 += p.w;
            }
            const float si = fsigmoid(s0);
            const float sf = fsigmoid(s1);
            const float gg = ftanh(s2);
            const float so = fsigmoid(s3);
            c = sf * c + si * gg;
            const float h = so * ftanh(c);
            g_htf[((size_t)bb * S_ + t) * H_ + j0 + jj] = f2tf(h);
        }

        // prefetch xg for t+1 BEFORE the barrier (latency hides behind spin)
        if (t + 1 < S_) {
            const size_t xrow = xbase + (size_t)(t + 1) * G4_;
            x0 = __ldcs(&g_xg[xrow]);
            x1 = __ldcs(&g_xg[xrow + H_]);
            x2 = __ldcs(&g_xg[xrow + 2 * H_]);
            x3 = __ldcs(&g_xg[xrow + 3 * H_]);
        }

        // grid barrier (single counter, tid0-only fences — R7 form)
        __syncthreads();
        if (tid == 0) {
            __threadfence();
            atomicAdd(&g_arrive, 1u);
            const unsigned target = (unsigned)(t + 1) * NCTA;
            while (*(volatile unsigned*)&g_arrive < target) { }
            __threadfence();
        }
        __syncthreads();
    }
}

// ---------------------------------------------------------------------------
extern "C" void kernel_launch(void* const* d_in, const int* in_sizes, int n_in,
                              void* d_out, int out_size)
{
    const int*   x    = (const int*)  d_in[0];
    const float* emb  = (const float*)d_in[1];
    const float* W_ih = (const float*)d_in[2];
    const float* W_hh = (const float*)d_in[3];
    const float* b_ih = (const float*)d_in[4];
    const float* b_hh = (const float*)d_in[5];
    const float* W_fc = (const float*)d_in[6];
    const float* b_fc = (const float*)d_in[7];
    float* out = (float*)d_out;

    float *p_xg; unsigned *p_htf;
    cudaGetSymbolAddress((void**)&p_xg,  g_xg);
    cudaGetSymbolAddress((void**)&p_htf, g_htf);
    cudaFuncSetAttribute(lstm_kernel,
                         cudaFuncAttributeMaxDynamicSharedMemorySize, SMEM_LSTM);

    // Phase 1: xg = emb[x] @ W_ih^T + b_ih + b_hh   [16384 x 4096], K=512
    gemm_tf32<true, false, 2><<<dim3(G4_ / BN, MR_ / BM), 256>>>(
        emb, x, W_ih, b_ih, b_hh, p_xg, MR_, G4_, E_);

    // Phase 2: recurrence (persistent, grid-barriered)
    reset_kernel<<<1, 1>>>();
    lstm_kernel<<<NCTA, 256, SMEM_LSTM>>>(W_hh);

    // Phase 3: logits = h @ W_fc^T + b_fc   [16384 x 5000], K=1024 (A is tf32 bits)
    gemm_tf32<false, true, 1><<<dim3((V_ + BN - 1) / BN, MR_ / BM), 256>>>(
        (const float*)p_htf, nullptr, W_fc, b_fc, nullptr, out, MR_, V_, H_);
}